// round 1
// baseline (speedup 1.0000x reference)
#include <cuda_runtime.h>

#define B_  32
#define CT  512
#define GC  128
#define H_  56
#define W_  56
#define HW  3136
#define FEATS_BASE (B_*GC*HW)   // 12,845,056 floats: mem section size

// Scratch (device-global; allocation inside kernel_launch is forbidden)
__device__ float g_q[B_*GC*HW];          // q post elu+1, layout [b][c][n], c = h*32+d
__device__ float g_k[B_*GC*HW];          // k post elu+1, same layout
__device__ float g_kv[B_*4*32*32];       // kv accumulators per (b,h,d,e)
__device__ float g_ksum[B_*4*32];        // k column sums per (b,h,d)

// ---------------------------------------------------------------------------
__global__ void zero_acc_kernel() {
    int i = blockIdx.x * blockDim.x + threadIdx.x;
    if (i < B_*4*32*32) g_kv[i] = 0.f;
    if (i < B_*4*32)    g_ksum[i] = 0.f;
}

// ---------------------------------------------------------------------------
// mem = x[:, :128] -> out[0 : B*128*HW), strided per batch, vectorized
__global__ void copy_mem_kernel(const float4* __restrict__ x, float4* __restrict__ out) {
    long i = (long)blockIdx.x * blockDim.x + threadIdx.x;
    const long total = (long)B_ * GC * HW / 4;
    if (i >= total) return;
    const int per_b = GC * HW / 4;
    int b = (int)(i / per_b);
    int r = (int)(i % per_b);
    out[i] = x[(long)b * (CT * HW / 4) + r];
}

// ---------------------------------------------------------------------------
// qk[b,o,n] = sum_c W[o,c] * x[b,128+c,n] + bias[o]; then elu()+1; store q/k.
// GEMM: M=256 (o), K=128 (c), N=3136 (n) per batch.
// Tile 128x128, 256 threads, 8x8 per thread.
__global__ __launch_bounds__(256) void qk_gemm_kernel(const float* __restrict__ x,
                                                      const float* __restrict__ wqk,
                                                      const float* __restrict__ bqk) {
    __shared__ float Ws[8][128];
    __shared__ float Xs[8][128];
    int b = blockIdx.z;
    int oBase = blockIdx.y * 128;
    int pBase = blockIdx.x * 128;
    int tid = threadIdx.x;
    int tx = tid & 15, ty = tid >> 4;
    const float* Xb = x + ((long)b * CT + GC) * HW;   // feat_att channels

    float acc[8][8];
    #pragma unroll
    for (int i = 0; i < 8; i++)
        #pragma unroll
        for (int j = 0; j < 8; j++) acc[i][j] = 0.f;

    for (int k0 = 0; k0 < 128; k0 += 8) {
        {   // W tile: 128 o x 8 k, transposed into Ws[k][o]
            int o_l = tid >> 1;
            int kk4 = (tid & 1) * 4;
            float4 w4 = *(const float4*)(wqk + (oBase + o_l) * 128 + k0 + kk4);
            Ws[kk4+0][o_l] = w4.x; Ws[kk4+1][o_l] = w4.y;
            Ws[kk4+2][o_l] = w4.z; Ws[kk4+3][o_l] = w4.w;
        }
        {   // X tile: 8 k x 128 p
            int kk = tid >> 5;
            int p4 = (tid & 31) * 4;
            int p = pBase + p4;
            float4 v = (p < HW) ? *(const float4*)(Xb + (long)(k0 + kk) * HW + p)
                                : make_float4(0.f, 0.f, 0.f, 0.f);
            *(float4*)&Xs[kk][p4] = v;
        }
        __syncthreads();
        #pragma unroll
        for (int kk = 0; kk < 8; kk++) {
            float4 a0 = *(float4*)&Ws[kk][ty * 8];
            float4 a1 = *(float4*)&Ws[kk][ty * 8 + 4];
            float4 b0 = *(float4*)&Xs[kk][tx * 8];
            float4 b1 = *(float4*)&Xs[kk][tx * 8 + 4];
            float av[8] = {a0.x, a0.y, a0.z, a0.w, a1.x, a1.y, a1.z, a1.w};
            float bv[8] = {b0.x, b0.y, b0.z, b0.w, b1.x, b1.y, b1.z, b1.w};
            #pragma unroll
            for (int i = 0; i < 8; i++)
                #pragma unroll
                for (int j = 0; j < 8; j++) acc[i][j] += av[i] * bv[j];
        }
        __syncthreads();
    }

    #pragma unroll
    for (int i = 0; i < 8; i++) {
        int o = oBase + ty * 8 + i;
        float bias = bqk[o];
        float* dst = (o < GC) ? (g_q + ((long)b * GC + o) * HW)
                              : (g_k + ((long)b * GC + (o - GC)) * HW);
        #pragma unroll
        for (int j = 0; j < 8; j++) {
            int p = pBase + tx * 8 + j;
            if (p < HW) {
                float v = acc[i][j] + bias;
                v = (v > 0.f) ? (v + 1.f) : __expf(v);   // elu(v)+1
                dst[p] = v;
            }
        }
    }
}

// ---------------------------------------------------------------------------
// ksum[b,h,d] += sum_n k ; kv[b,h,d,e] += sum_n k[d,n]*v[e,n]  (v = raw feat_att)
__global__ __launch_bounds__(256) void kv_reduce_kernel(const float* __restrict__ x) {
    __shared__ float Ks[32 * 129];
    __shared__ float Vs[32 * 129];
    int b = blockIdx.z, h = blockIdx.y;
    int p0 = blockIdx.x * 128;
    int tid = threadIdx.x;
    const float* Kb = g_k + ((long)b * GC + h * 32) * HW;
    const float* Vb = x   + ((long)b * CT + GC + h * 32) * HW;

    for (int idx = tid; idx < 4096; idx += 256) {
        int d = idx >> 7, p = idx & 127;
        bool ok = (p0 + p) < HW;
        Ks[d * 129 + p] = ok ? Kb[(long)d * HW + p0 + p] : 0.f;
        Vs[d * 129 + p] = ok ? Vb[(long)d * HW + p0 + p] : 0.f;
    }
    __syncthreads();

    int d = tid >> 3;
    int e0 = (tid & 7) * 4;
    float a0 = 0.f, a1 = 0.f, a2 = 0.f, a3 = 0.f;
    #pragma unroll 4
    for (int n = 0; n < 128; n++) {
        float kd = Ks[d * 129 + n];
        a0 += kd * Vs[(e0 + 0) * 129 + n];
        a1 += kd * Vs[(e0 + 1) * 129 + n];
        a2 += kd * Vs[(e0 + 2) * 129 + n];
        a3 += kd * Vs[(e0 + 3) * 129 + n];
    }
    float* kvdst = g_kv + (((long)(b * 4 + h) * 32 + d) * 32 + e0);
    atomicAdd(kvdst + 0, a0);
    atomicAdd(kvdst + 1, a1);
    atomicAdd(kvdst + 2, a2);
    atomicAdd(kvdst + 3, a3);

    if (tid < 32) {
        float s = 0.f;
        for (int n = 0; n < 128; n++) s += Ks[tid * 129 + n];
        atomicAdd(g_ksum + (b * 4 + h) * 32 + tid, s);
    }
}

// ---------------------------------------------------------------------------
// att[n,e] = z[n] * sum_d q[n,d] * (kv[d,e]/HW), z[n]=1/(sum_d q[n,d]*kmean[d]+1e-6)
__global__ __launch_bounds__(256) void att_kernel(float* __restrict__ out) {
    __shared__ float kvs[4096];   // [h][d][e] scaled by 1/HW
    __shared__ float kms[128];    // [h][d]
    int b = blockIdx.y;
    int p0 = blockIdx.x * 128;
    int tid = threadIdx.x;
    const float invHW = 1.f / (float)HW;
    for (int idx = tid; idx < 4096; idx += 256) kvs[idx] = g_kv[(long)b * 4096 + idx] * invHW;
    if (tid < 128) kms[tid] = g_ksum[b * 128 + tid] * invHW;
    __syncthreads();

    int h = tid >> 6, lp = tid & 63;
    int n1 = p0 + lp, n2 = p0 + 64 + lp;
    bool v1 = n1 < HW, v2 = n2 < HW;
    const float* qb = g_q + ((long)b * GC + h * 32) * HW;

    float q1[32], q2[32];
    #pragma unroll
    for (int d = 0; d < 32; d++) {
        q1[d] = v1 ? qb[(long)d * HW + n1] : 0.f;
        q2[d] = v2 ? qb[(long)d * HW + n2] : 0.f;
    }
    float s1 = 0.f, s2 = 0.f;
    #pragma unroll
    for (int d = 0; d < 32; d++) {
        float km = kms[h * 32 + d];
        s1 += q1[d] * km;
        s2 += q2[d] * km;
    }
    float z1 = 1.f / (s1 + 1e-6f);
    float z2 = 1.f / (s2 + 1e-6f);

    float* ob = out + FEATS_BASE + ((long)b * 384 + h * 32) * HW;
    #pragma unroll
    for (int e = 0; e < 32; e++) {
        float a1 = 0.f, a2 = 0.f;
        #pragma unroll
        for (int d = 0; d < 32; d++) {
            float kvv = kvs[(h * 32 + d) * 32 + e];
            a1 += q1[d] * kvv;
            a2 += q2[d] * kvv;
        }
        if (v1) ob[(long)e * HW + n1] = a1 * z1;
        if (v2) ob[(long)e * HW + n2] = a2 * z2;
    }
}

// ---------------------------------------------------------------------------
// 3x3 depthwise conv on channels [256,384), pad 1
__global__ void dw3_kernel(const float* __restrict__ x, const float* __restrict__ w,
                           const float* __restrict__ bias, float* __restrict__ out) {
    int n = blockIdx.x * 256 + threadIdx.x;
    if (n >= HW) return;
    int c = blockIdx.y, b = blockIdx.z;
    int yy = n / W_, xx = n % W_;
    const float* in = x + ((long)b * CT + 2 * GC + c) * HW;
    float wr[9];
    #pragma unroll
    for (int i = 0; i < 9; i++) wr[i] = w[c * 9 + i];
    float acc = bias[c];
    #pragma unroll
    for (int ky = 0; ky < 3; ky++) {
        int iy = yy + ky - 1;
        if (iy < 0 || iy >= H_) continue;
        #pragma unroll
        for (int kx = 0; kx < 3; kx++) {
            int ix = xx + kx - 1;
            if (ix < 0 || ix >= W_) continue;
            acc += wr[ky * 3 + kx] * in[iy * W_ + ix];
        }
    }
    out[FEATS_BASE + ((long)b * 384 + GC + c) * HW + n] = acc;
}

// ---------------------------------------------------------------------------
// 7x7 depthwise conv on channels [384,512), pad 3. Row-tiled: block covers a
// full 56-wide row strip of 8 output rows; each thread computes 4 outputs in x.
__global__ __launch_bounds__(112) void dw7_kernel(const float* __restrict__ x,
                                                  const float* __restrict__ w,
                                                  const float* __restrict__ bias,
                                                  float* __restrict__ out) {
    __shared__ float tile[14][64];   // rows y0-3 .. y0+10, cols x-3 .. x+58 (62 used)
    __shared__ float ws[49];
    int y0 = blockIdx.x * 8;
    int c = blockIdx.y, b = blockIdx.z;
    int tid = threadIdx.x;
    const float* in = x + ((long)b * CT + 3 * GC + c) * HW;

    if (tid < 49) ws[tid] = w[c * 49 + tid];
    for (int idx = tid; idx < 14 * 62; idx += 112) {
        int r = idx / 62, cc = idx % 62;
        int iy = y0 - 3 + r, ix = cc - 3;
        tile[r][cc] = (iy >= 0 && iy < H_ && ix >= 0 && ix < W_) ? in[iy * W_ + ix] : 0.f;
    }
    __syncthreads();

    int gx = tid % 14, gy = tid / 14;   // gy in [0,8)
    int xb = gx * 4;
    float bb = bias[c];
    float a0 = bb, a1 = bb, a2 = bb, a3 = bb;
    #pragma unroll
    for (int ky = 0; ky < 7; ky++) {
        const float* row = &tile[gy + ky][xb];
        float r[10];
        #pragma unroll
        for (int i = 0; i < 10; i++) r[i] = row[i];
        #pragma unroll
        for (int kx = 0; kx < 7; kx++) {
            float wv = ws[ky * 7 + kx];
            a0 += wv * r[kx + 0];
            a1 += wv * r[kx + 1];
            a2 += wv * r[kx + 2];
            a3 += wv * r[kx + 3];
        }
    }
    float* ob = out + FEATS_BASE + ((long)b * 384 + 2 * GC + c) * HW + (y0 + gy) * W_ + xb;
    ob[0] = a0; ob[1] = a1; ob[2] = a2; ob[3] = a3;
}

// ---------------------------------------------------------------------------
extern "C" void kernel_launch(void* const* d_in, const int* in_sizes, int n_in,
                              void* d_out, int out_size) {
    const float* x     = (const float*)d_in[0];
    const float* w_dw1 = (const float*)d_in[1];
    const float* b_dw1 = (const float*)d_in[2];
    const float* w_dw2 = (const float*)d_in[3];
    const float* b_dw2 = (const float*)d_in[4];
    const float* w_qk  = (const float*)d_in[5];
    const float* b_qk  = (const float*)d_in[6];
    float* out = (float*)d_out;

    zero_acc_kernel<<<512, 256>>>();
    copy_mem_kernel<<<(B_ * GC * HW / 4 + 255) / 256, 256>>>((const float4*)x, (float4*)out);
    qk_gemm_kernel<<<dim3(25, 2, B_), 256>>>(x, w_qk, b_qk);
    kv_reduce_kernel<<<dim3(25, 4, B_), 256>>>(x);
    att_kernel<<<dim3(25, B_), 256>>>(out);
    dw3_kernel<<<dim3((HW + 255) / 256, GC, B_), 256>>>(x, w_dw1, b_dw1, out);
    dw7_kernel<<<dim3(7, GC, B_), 112>>>(x, w_dw2, b_dw2, out);
}